// round 14
// baseline (speedup 1.0000x reference)
#include <cuda_runtime.h>
#include <math.h>

#define Bn 64
#define Sn 512
#define Hn 1024
#define Ln 9
#define CH 16

// Scratch (no allocations allowed) — plain stores, no global value atomics
__device__ float g_em[(size_t)Bn * Sn * Ln];   // emissions (log domain), 1.18 MB
__device__ float g_part[128];                  // per-gemm-block score partials
__device__ float g_half[128 * 81];             // per (batch, half) combined matrices
__device__ float g_hlog[128];                  // per-half sum of chunk log norms
__device__ int   g_cnt;                        // k_crf arrival counter (reset by k_gemm)

#define FMA2(acc, a, b) asm("fma.rn.f32x2 %0, %1, %2, %0;" : "+l"(acc) : "l"(a), "l"(b))

__device__ __forceinline__ unsigned long long pk2(float lo, float hi) {
    unsigned long long r;
    asm("mov.b64 %0, {%1, %2};" : "=l"(r) : "f"(lo), "f"(hi));
    return r;
}
__device__ __forceinline__ float unpk_sum(unsigned long long v) {
    float lo, hi;
    asm("mov.b64 {%0, %1}, %2;" : "=f"(lo), "=f"(hi) : "l"(v));
    return lo + hi;
}

// ---------------------------------------------------------------------------
// Kernel 1: emissions GEMM + numerator score fused in the epilogue.
// 128 blocks x 256 thr; warp = 8 row-slots x 4-lane quads; 4 rows/lane with
// W float4 reuse, packed f32x2 FMA, and an explicit DEPTH-2 double-buffered
// prefetch of the X loads (loads for j+2 issued after consuming j).
// ---------------------------------------------------------------------------
__global__ void __launch_bounds__(256, 1) k_gemm(const float* __restrict__ x,
                                                 const float* __restrict__ W,
                                                 const float* __restrict__ bias,
                                                 const int* __restrict__ tags,
                                                 const int* __restrict__ mask,
                                                 const float* __restrict__ startT,
                                                 const float* __restrict__ T) {
    __shared__ float sW[Ln * Hn];
    __shared__ float sb[Ln];
    __shared__ float sT[81];
    __shared__ float sst[Ln];
    __shared__ float sred[8];
    int tid = threadIdx.x;
    if (blockIdx.x == 0 && tid == 0) g_cnt = 0;   // safe: k_crf is stream-ordered after
    for (int i = tid; i < Ln * Hn / 4; i += 256)
        ((float4*)sW)[i] = ((const float4*)W)[i];
    if (tid < Ln) sb[tid] = bias[tid];
    if (tid >= 32 && tid < 32 + 81) sT[tid - 32] = T[tid - 32];
    if (tid >= 128 && tid < 128 + Ln) sst[tid - 128] = startT[tid - 128];
    __syncthreads();

    int lane = tid & 31;
    int warp = tid >> 5;                     // 0..7
    int rw = lane >> 2;                      // row slot 0..7
    int quad = lane & 3;                     // k-slice
    size_t row0 = (size_t)blockIdx.x * 256 + warp * 32 + rw * 4;

    const ulonglong2* xr = (const ulonglong2*)(x + row0 * Hn);  // 256 u2 per row

    unsigned long long acc[4][Ln];
#pragma unroll
    for (int r = 0; r < 4; r++)
#pragma unroll
        for (int l = 0; l < Ln; l++) acc[r][l] = 0ull;

    // depth-2 pipeline: even/odd register buffers
    ulonglong2 bufE[4], bufO[4];
#pragma unroll
    for (int r = 0; r < 4; r++) {
        bufE[r] = xr[r * 256 + quad];            // j=0
        bufO[r] = xr[r * 256 + quad + 4];        // j=1
    }

#pragma unroll 2
    for (int j = 0; j < 64; j++) {
        ulonglong2 x0, x1, x2, x3;
        if (j & 1) { x0 = bufO[0]; x1 = bufO[1]; x2 = bufO[2]; x3 = bufO[3]; }
        else       { x0 = bufE[0]; x1 = bufE[1]; x2 = bufE[2]; x3 = bufE[3]; }
        int kv = quad + j * 4;
#pragma unroll
        for (int l = 0; l < Ln; l++) {
            ulonglong2 wv = ((const ulonglong2*)(sW + l * Hn))[kv];
            FMA2(acc[0][l], x0.x, wv.x); FMA2(acc[0][l], x0.y, wv.y);
            FMA2(acc[1][l], x1.x, wv.x); FMA2(acc[1][l], x1.y, wv.y);
            FMA2(acc[2][l], x2.x, wv.x); FMA2(acc[2][l], x2.y, wv.y);
            FMA2(acc[3][l], x3.x, wv.x); FMA2(acc[3][l], x3.y, wv.y);
        }
        // refill the buffer just consumed with j+2 (not needed for 2 iters)
        if (j < 62) {
            int kvn = quad + (j + 2) * 4;
            if (j & 1) {
#pragma unroll
                for (int r = 0; r < 4; r++) bufO[r] = xr[r * 256 + kvn];
            } else {
#pragma unroll
                for (int r = 0; r < 4; r++) bufE[r] = xr[r * 256 + kvn];
            }
        }
    }

    // per-row tag/mask metadata (quad==0 lanes own the rows)
    int tg[4], pv[4], mk4[4];
    if (quad == 0) {
#pragma unroll
        for (int r = 0; r < 4; r++) {
            size_t row = row0 + r;
            int s = (int)(row & (Sn - 1));
            tg[r] = tags[row];
            mk4[r] = mask[row];
            pv[r] = (s > 0) ? tags[row - 1] : 0;
        }
    }

    float score = 0.f;
#pragma unroll
    for (int r = 0; r < 4; r++) {
        float ev = 0.f;
#pragma unroll
        for (int l = 0; l < Ln; l++) {
            float v = unpk_sum(acc[r][l]);
            v += __shfl_xor_sync(0xffffffffu, v, 1);
            v += __shfl_xor_sync(0xffffffffu, v, 2);
            if (quad == 0) {
                float vf = v + sb[l];
                g_em[(row0 + r) * Ln + l] = vf;
                if (l == tg[r]) ev = vf;
            }
        }
        if (quad == 0) {
            int s = (int)((row0 + r) & (Sn - 1));
            if (s == 0)           score += sst[tg[r]] + ev;
            else if (mk4[r] != 0) score += sT[pv[r] * 9 + tg[r]] + ev;
        }
    }
#pragma unroll
    for (int o = 16; o > 0; o >>= 1) score += __shfl_xor_sync(0xffffffffu, score, o);
    if (lane == 0) sred[warp] = score;
    __syncthreads();
    if (warp == 0) {
        float t = (lane < 8) ? sred[lane] : 0.f;
#pragma unroll
        for (int o = 4; o > 0; o >>= 1) t += __shfl_xor_sync(0xffffffffu, t, o);
        if (lane == 0) g_part[blockIdx.x] = t;
    }
}

// ---------------------------------------------------------------------------
// Kernel 2: CRF partition function. Grid 128 = (batch, half); block 512 thr
// = 16 warps; warp w folds chunk h*16+w (16 steps) in the EXP domain using
// 12-float padded rows (LDS.128 + FMA2), then a 4-level in-block tree gives
// the half-sequence matrix (each product /9). Last-arriving block combines
// halves, finalizes logZ, end terms, mask counts, score partials -> out.
// ---------------------------------------------------------------------------
__global__ void __launch_bounds__(512, 1) k_crf(const int* __restrict__ tags,
                                                const int* __restrict__ mask,
                                                const float* __restrict__ startT,
                                                const float* __restrict__ endT,
                                                const float* __restrict__ T,
                                                float* __restrict__ out) {
    __shared__ __align__(16) float sE[16][2][108];  // padded 9x12 ping-pong, 13.8 KB
    __shared__ float bufA[16 * 81];
    __shared__ float bufB[8 * 81];
    __shared__ float sTe[81];
    __shared__ float slog[16];
    __shared__ int sflag;
    // finalize-only
    __shared__ float sZ[Bn];
    __shared__ float sa0[Bn * Ln];
    __shared__ float see[Ln];
    __shared__ float sEndT[Bn];
    __shared__ float sred2[16];

    int blk = blockIdx.x;
    int b = blk >> 1, h = blk & 1;
    int tid = threadIdx.x;
    int lane = tid & 31, w = tid >> 5;

    if (tid == 0) sflag = 0;
    if (tid < 81) sTe[tid] = __expf(T[tid]);
    // zero pad columns (9..11) of both ping-pong buffers for this warp
    for (int t = lane; t < 54; t += 32) {
        int buf = t / 27, r2 = t % 27;
        sE[w][buf][(r2 / 3) * 12 + 9 + (r2 % 3)] = 0.f;
    }
    __syncthreads();   // sTe + pads visible

    // ---- per-warp chunk scan ----
    int e0 = lane, e1 = lane + 32, e2 = lane + 64;
    bool act2 = (e2 < 81);
    int i0 = e0 / 9, j0 = e0 % 9;
    int i1 = e1 / 9, j1 = e1 % 9;
    int i2 = act2 ? e2 / 9 : 0, j2 = act2 ? e2 % 9 : 0;

    // packed exp(T) columns: 6 u64 (12 floats, pad 0) per owned column
    unsigned long long p0[6], p1[6], p2[6];
#pragma unroll
    for (int t = 0; t < 6; t++) {
        int k0 = 2 * t, k1 = 2 * t + 1;
        float a0c = (k0 < 9) ? sTe[k0 * 9 + j0] : 0.f;
        float a1c = (k1 < 9) ? sTe[k1 * 9 + j0] : 0.f;
        p0[t] = pk2(a0c, a1c);
        float b0c = (k0 < 9) ? sTe[k0 * 9 + j1] : 0.f;
        float b1c = (k1 < 9) ? sTe[k1 * 9 + j1] : 0.f;
        p1[t] = pk2(b0c, b1c);
        float c0c = (act2 && k0 < 9) ? sTe[k0 * 9 + j2] : 0.f;
        float c1c = (act2 && k1 < 9) ? sTe[k1 * 9 + j2] : 0.f;
        p2[t] = pk2(c0c, c1c);
    }
    float eTd0 = sTe[i0 * 9 + j0];
    float eTd1 = sTe[i1 * 9 + j1];
    float eTd2 = act2 ? sTe[i2 * 9 + j2] : 0.f;

    int c = h * 16 + w;
    const float* emb = g_em + (size_t)b * Sn * Ln;
    const int* mb = mask + b * Sn;
    int s0 = 1 + c * CH;
    int send = min(Sn, s0 + CH);

    int mnext = mb[s0];
    float q0 = emb[s0 * 9 + j0];
    float q1 = emb[s0 * 9 + j1];
    float q2 = act2 ? emb[s0 * 9 + j2] : 0.f;

    int cur = 0;
    bool have = false;
    for (int s = s0; s < send; s++) {
        int mcur = mnext;
        float a0 = q0, a1 = q1, a2 = q2;
        if (s + 1 < send) {
            mnext = mb[s + 1];
            q0 = emb[(s + 1) * 9 + j0];
            q1 = emb[(s + 1) * 9 + j1];
            q2 = act2 ? emb[(s + 1) * 9 + j2] : 0.f;
        }
        if (mcur == 0) continue;         // uniform per warp
        float x0 = __expf(a0);
        float x1 = __expf(a1);
        float x2 = act2 ? __expf(a2) : 0.f;
        if (!have) {
            float* E = sE[w][cur];
            E[i0 * 12 + j0] = eTd0 * x0;
            E[i1 * 12 + j1] = eTd1 * x1;
            if (act2) E[i2 * 12 + j2] = eTd2 * x2;
            have = true;
            __syncwarp();
        } else {
            const ulonglong2* E = (const ulonglong2*)sE[w][cur];  // row i at E[i*3..]
            unsigned long long ac0 = 0ull, ac1 = 0ull, ac2 = 0ull;
            {
                ulonglong2 ra = E[i0 * 3], rb = E[i0 * 3 + 1], rc = E[i0 * 3 + 2];
                FMA2(ac0, ra.x, p0[0]); FMA2(ac0, ra.y, p0[1]);
                FMA2(ac0, rb.x, p0[2]); FMA2(ac0, rb.y, p0[3]);
                FMA2(ac0, rc.x, p0[4]); FMA2(ac0, rc.y, p0[5]);
            }
            {
                ulonglong2 ra = E[i1 * 3], rb = E[i1 * 3 + 1], rc = E[i1 * 3 + 2];
                FMA2(ac1, ra.x, p1[0]); FMA2(ac1, ra.y, p1[1]);
                FMA2(ac1, rb.x, p1[2]); FMA2(ac1, rb.y, p1[3]);
                FMA2(ac1, rc.x, p1[4]); FMA2(ac1, rc.y, p1[5]);
            }
            if (act2) {
                ulonglong2 ra = E[i2 * 3], rb = E[i2 * 3 + 1], rc = E[i2 * 3 + 2];
                FMA2(ac2, ra.x, p2[0]); FMA2(ac2, ra.y, p2[1]);
                FMA2(ac2, rb.x, p2[2]); FMA2(ac2, rb.y, p2[3]);
                FMA2(ac2, rc.x, p2[4]); FMA2(ac2, rc.y, p2[5]);
            }
            float* En = sE[w][cur ^ 1];
            En[i0 * 12 + j0] = unpk_sum(ac0) * x0;
            En[i1 * 12 + j1] = unpk_sum(ac1) * x1;
            if (act2) En[i2 * 12 + j2] = unpk_sum(ac2) * x2;
            cur ^= 1;
            __syncwarp();
        }
    }

    // normalize into compact bufA, keep log(max)
    float* outm = bufA + w * 81;
    if (have) {
        const float* E = sE[w][cur];
        float v0 = E[i0 * 12 + j0], v1 = E[i1 * 12 + j1];
        float v2 = act2 ? E[i2 * 12 + j2] : 0.f;
        float m = fmaxf(fmaxf(v0, v1), v2);
        m = fmaxf(m, __shfl_xor_sync(0xffffffffu, m, 1));
        m = fmaxf(m, __shfl_xor_sync(0xffffffffu, m, 2));
        m = fmaxf(m, __shfl_xor_sync(0xffffffffu, m, 4));
        m = fmaxf(m, __shfl_xor_sync(0xffffffffu, m, 8));
        m = fmaxf(m, __shfl_xor_sync(0xffffffffu, m, 16));
        m = fmaxf(m, 1e-35f);
        float rcp = 1.f / m;
        outm[e0] = v0 * rcp; outm[e1] = v1 * rcp; if (act2) outm[e2] = v2 * rcp;
        if (lane == 0) slog[w] = __logf(m);
    } else {
        outm[e0] = (i0 == j0) ? 1.f : 0.f;
        outm[e1] = (i1 == j1) ? 1.f : 0.f;
        if (act2) outm[e2] = (i2 == j2) ? 1.f : 0.f;
        if (lane == 0) slog[w] = 0.f;
    }
    __syncthreads();

    // ---- 4-level tree: 16 -> 1, each product scaled by 1/9 ----
    float* src = bufA;
    float* dst = bufB;
    for (int np = 8; np >= 1; np >>= 1) {
        for (int e = tid; e < np * 81; e += 512) {
            int pp = e / 81, r = e % 81, i = r / 9, j = r % 9;
            const float* Am = src + 2 * pp * 81;
            const float* Bm = src + (2 * pp + 1) * 81;
            float s = 0.f;
#pragma unroll
            for (int k = 0; k < 9; k++) s += Am[i * 9 + k] * Bm[k * 9 + j];
            dst[e] = s * (1.f / 9.f);
        }
        __syncthreads();
        float* t = src; src = dst; dst = t;
    }
    // half-matrix in src[0..81) (== bufA)

    for (int e = tid; e < 81; e += 512) g_half[blk * 81 + e] = src[e];
    if (w == 0) {
        float lg = (lane < 16) ? slog[lane] : 0.f;
#pragma unroll
        for (int o = 8; o > 0; o >>= 1) lg += __shfl_xor_sync(0xffffffffu, lg, o);
        if (lane == 0) {
            g_hlog[blk] = lg;
            __threadfence();
            int old = atomicAdd(&g_cnt, 1);
            if (old == 127) sflag = 1;
        }
    }
    __syncthreads();
    if (!sflag) return;

    // ---- last-arriving block: combine halves + finalize everything ----
    if (tid < Bn) sZ[tid] = 0.f;
    for (int idx = tid; idx < Bn * Ln; idx += 512) {
        int b2 = idx / Ln, i = idx % Ln;
        sa0[idx] = __expf(startT[i] + g_em[(size_t)b2 * Sn * Ln + i]);
    }
    if (tid >= 128 && tid < 128 + Ln) see[tid - 128] = __expf(endT[tid - 128]);
    // mask counts + end transition per batch (warp per batch, strided)
    for (int b2 = w; b2 < Bn; b2 += 16) {
        int cnt = 0;
        for (int t = 0; t < 16; t++) {
            int mk = (mask[b2 * Sn + t * 32 + lane] != 0);
            cnt += __popc(__ballot_sync(0xffffffffu, mk));
        }
        if (lane == 0) sEndT[b2] = endT[tags[b2 * Sn + max(cnt, 1) - 1]];
    }
    __syncthreads();

    for (int idx = tid; idx < Bn * 81; idx += 512) {
        int b2 = idx / 81, r = idx % 81, i = r / 9, j = r % 9;
        const float* Am = g_half + (2 * b2) * 81;
        const float* Bm = g_half + (2 * b2 + 1) * 81;
        float s = 0.f;
#pragma unroll
        for (int k = 0; k < 9; k++) s += Am[i * 9 + k] * Bm[k * 9 + j];
        atomicAdd(&sZ[b2], sa0[b2 * Ln + i] * s * see[j]);
    }
    __syncthreads();

    // total = sum_b (logZ_b - endT term) - sum g_part   (30*ln9 from tree scaling)
    float v = 0.f;
    if (tid < Bn)
        v = __logf(sZ[tid]) + 65.91673737f + g_hlog[2 * tid] + g_hlog[2 * tid + 1] - sEndT[tid];
    else if (tid < Bn + 128)
        v = -g_part[tid - Bn];
#pragma unroll
    for (int o = 16; o > 0; o >>= 1) v += __shfl_xor_sync(0xffffffffu, v, o);
    if (lane == 0) sred2[w] = v;
    __syncthreads();
    if (w == 0) {
        float t = (lane < 16) ? sred2[lane] : 0.f;
#pragma unroll
        for (int o = 8; o > 0; o >>= 1) t += __shfl_xor_sync(0xffffffffu, t, o);
        if (lane == 0) out[0] = t;
    }
}

// ---------------------------------------------------------------------------
extern "C" void kernel_launch(void* const* d_in, const int* in_sizes, int n_in,
                              void* d_out, int out_size) {
    const float* x      = (const float*)d_in[0];   // (64,512,1024) f32
    const int*   tags   = (const int*)d_in[1];     // (64,512) i32
    const int*   mask   = (const int*)d_in[2];     // (64,512) bool -> i32
    const float* W      = (const float*)d_in[3];   // (9,1024) f32
    const float* bias   = (const float*)d_in[4];   // (9,)
    const float* startT = (const float*)d_in[5];   // (9,)
    const float* endT   = (const float*)d_in[6];   // (9,)
    const float* T      = (const float*)d_in[7];   // (9,9)

    k_gemm<<<128, 256>>>(x, W, bias, tags, mask, startT, T);
    k_crf <<<128, 512>>>(tags, mask, startT, endT, T, (float*)d_out);
}

// round 17
// speedup vs baseline: 1.0656x; 1.0656x over previous
#include <cuda_runtime.h>
#include <math.h>

#define Bn 64
#define Sn 512
#define Hn 1024
#define Ln 9
#define CH 16
#define GEMM_GRID 148
#define NTILES 2048         // 32768 rows / 16 rows per warp-tile

// Scratch (no allocations allowed) — plain stores, no global value atomics
__device__ float g_em[(size_t)Bn * Sn * Ln];   // emissions (log domain), 1.18 MB
__device__ float g_part[GEMM_GRID];            // per-gemm-block score partials
__device__ float g_half[128 * 81];             // per (batch, half) combined matrices
__device__ float g_hlog[128];                  // per-half sum of chunk log norms
__device__ int   g_cnt;                        // k_crf arrival counter (reset by k_gemm)

#define FMA2(acc, a, b) asm("fma.rn.f32x2 %0, %1, %2, %0;" : "+l"(acc) : "l"(a), "l"(b))

__device__ __forceinline__ float unpk_sum(unsigned long long v) {
    float lo, hi;
    asm("mov.b64 {%0, %1}, %2;" : "=f"(lo), "=f"(hi) : "l"(v));
    return lo + hi;
}

// ---------------------------------------------------------------------------
// Kernel 1: emissions GEMM + numerator score fused in the epilogue.
// 148 blocks x 512 thr (4 warps/SMSP, every SM busy). Warp-tile = 16 rows
// (8 slots x 4-lane quads, 2 rows/lane); 2048 tiles assigned round-robin
// tile = w*148 + bid so all SMs carry 13-14 busy warps. Depth-2 register
// double-buffered prefetch of X; W float4 from smem; packed f32x2 FMA.
// ---------------------------------------------------------------------------
__global__ void __launch_bounds__(512, 1) k_gemm(const float* __restrict__ x,
                                                 const float* __restrict__ W,
                                                 const float* __restrict__ bias,
                                                 const int* __restrict__ tags,
                                                 const int* __restrict__ mask,
                                                 const float* __restrict__ startT,
                                                 const float* __restrict__ T) {
    __shared__ float sW[Ln * Hn];
    __shared__ float sb[Ln];
    __shared__ float sT[81];
    __shared__ float sst[Ln];
    __shared__ float sred[16];
    int tid = threadIdx.x;
    if (blockIdx.x == 0 && tid == 0) g_cnt = 0;   // k_crf is stream-ordered after
    for (int i = tid; i < Ln * Hn / 4; i += 512)
        ((float4*)sW)[i] = ((const float4*)W)[i];
    if (tid < Ln) sb[tid] = bias[tid];
    if (tid >= 32 && tid < 32 + 81) sT[tid - 32] = T[tid - 32];
    if (tid >= 128 && tid < 128 + Ln) sst[tid - 128] = startT[tid - 128];
    __syncthreads();

    int lane = tid & 31;
    int warp = tid >> 5;                     // 0..15
    int tile = warp * GEMM_GRID + blockIdx.x;
    float score = 0.f;

    if (tile < NTILES) {
        int rw = lane >> 2;                  // row slot 0..7
        int quad = lane & 3;                 // k-slice
        size_t row0 = (size_t)tile * 16 + rw * 2;   // 2 rows: row0, row0+1

        const ulonglong2* xr0 = (const ulonglong2*)(x + row0 * Hn);  // 256 u2/row
        const ulonglong2* xr1 = xr0 + 256;

        unsigned long long acc[2][Ln];
#pragma unroll
        for (int r = 0; r < 2; r++)
#pragma unroll
            for (int l = 0; l < Ln; l++) acc[r][l] = 0ull;

        // depth-2 register double buffer
        ulonglong2 bE0 = xr0[quad],     bE1 = xr1[quad];
        ulonglong2 bO0 = xr0[quad + 4], bO1 = xr1[quad + 4];

#pragma unroll 2
        for (int j = 0; j < 64; j++) {
            ulonglong2 x0 = (j & 1) ? bO0 : bE0;
            ulonglong2 x1 = (j & 1) ? bO1 : bE1;
            int kv = quad + j * 4;
#pragma unroll
            for (int l = 0; l < Ln; l++) {
                ulonglong2 wv = ((const ulonglong2*)(sW + l * Hn))[kv];
                FMA2(acc[0][l], x0.x, wv.x); FMA2(acc[0][l], x0.y, wv.y);
                FMA2(acc[1][l], x1.x, wv.x); FMA2(acc[1][l], x1.y, wv.y);
            }
            if (j < 62) {
                int kvn = kv + 8;
                if (j & 1) { bO0 = xr0[kvn]; bO1 = xr1[kvn]; }
                else       { bE0 = xr0[kvn]; bE1 = xr1[kvn]; }
            }
        }

        // per-row tag/mask metadata (quad==0 lanes own the rows)
        int tg[2], pv[2], mk2[2];
        if (quad == 0) {
#pragma unroll
            for (int r = 0; r < 2; r++) {
                size_t row = row0 + r;
                int s = (int)(row & (Sn - 1));
                tg[r] = tags[row];
                mk2[r] = mask[row];
                pv[r] = (s > 0) ? tags[row - 1] : 0;
            }
        }

#pragma unroll
        for (int r = 0; r < 2; r++) {
            float ev = 0.f;
#pragma unroll
            for (int l = 0; l < Ln; l++) {
                float v = unpk_sum(acc[r][l]);
                v += __shfl_xor_sync(0xffffffffu, v, 1);
                v += __shfl_xor_sync(0xffffffffu, v, 2);
                if (quad == 0) {
                    float vf = v + sb[l];
                    g_em[(row0 + r) * Ln + l] = vf;
                    if (l == tg[r]) ev = vf;
                }
            }
            if (quad == 0) {
                int s = (int)((row0 + r) & (Sn - 1));
                if (s == 0)           score += sst[tg[r]] + ev;
                else if (mk2[r] != 0) score += sT[pv[r] * 9 + tg[r]] + ev;
            }
        }
    }

    // block reduce (idle warps / non-quad0 lanes contribute 0)
#pragma unroll
    for (int o = 16; o > 0; o >>= 1) score += __shfl_xor_sync(0xffffffffu, score, o);
    if (lane == 0) sred[warp] = score;
    __syncthreads();
    if (warp == 0) {
        float t = (lane < 16) ? sred[lane] : 0.f;
#pragma unroll
        for (int o = 8; o > 0; o >>= 1) t += __shfl_xor_sync(0xffffffffu, t, o);
        if (lane == 0) g_part[blockIdx.x] = t;
    }
}

// ---------------------------------------------------------------------------
// Kernel 2: CRF partition function. Grid 128 = (batch, half); block 512 thr
// = 16 warps; warp w folds chunk h*16+w (CH=16 steps) in the EXP domain
// (scalar smem rows — broadcast LDS, short dep chains; the R13-proven form),
// then a 4-level in-block tree (products scaled 1/9) gives the half matrix.
// Last-arriving block combines halves and finalizes everything -> out.
// ---------------------------------------------------------------------------
__global__ void __launch_bounds__(512, 1) k_crf(const int* __restrict__ tags,
                                                const int* __restrict__ mask,
                                                const float* __restrict__ startT,
                                                const float* __restrict__ endT,
                                                const float* __restrict__ T,
                                                float* __restrict__ out) {
    __shared__ float sE[16][2][81];      // ping-pong scan buffers, 10.1 KB
    __shared__ float bufA[16 * 81];
    __shared__ float bufB[8 * 81];
    __shared__ float sTe[81];
    __shared__ float slog[16];
    __shared__ int sflag;
    // finalize-only
    __shared__ float sZ[Bn];
    __shared__ float sa0[Bn * Ln];
    __shared__ float see[Ln];
    __shared__ float sEndT[Bn];
    __shared__ float sred2[16];

    int blk = blockIdx.x;
    int b = blk >> 1, h = blk & 1;
    int tid = threadIdx.x;
    int lane = tid & 31, w = tid >> 5;

    if (tid == 0) sflag = 0;
    if (tid < 81) sTe[tid] = __expf(T[tid]);
    __syncthreads();

    // ---- per-warp chunk scan (chunk c = h*16 + w) ----
    int e0 = lane, e1 = lane + 32, e2 = lane + 64;
    bool act2 = (e2 < 81);
    int i0 = e0 / 9, j0 = e0 % 9;
    int i1 = e1 / 9, j1 = e1 % 9;
    int i2 = act2 ? e2 / 9 : 0, j2 = act2 ? e2 % 9 : 0;

    float eT0[9], eT1[9], eT2[9];
#pragma unroll
    for (int k = 0; k < 9; k++) {
        eT0[k] = sTe[k * 9 + j0];
        eT1[k] = sTe[k * 9 + j1];
        eT2[k] = act2 ? sTe[k * 9 + j2] : 0.f;
    }
    float eTd0 = sTe[i0 * 9 + j0];
    float eTd1 = sTe[i1 * 9 + j1];
    float eTd2 = act2 ? sTe[i2 * 9 + j2] : 0.f;

    int c = h * 16 + w;
    const float* emb = g_em + (size_t)b * Sn * Ln;
    const int* mb = mask + b * Sn;
    int s0 = 1 + c * CH;
    int send = min(Sn, s0 + CH);

    int mnext = mb[s0];
    float q0 = emb[s0 * 9 + j0];
    float q1 = emb[s0 * 9 + j1];
    float q2 = act2 ? emb[s0 * 9 + j2] : 0.f;

    int cur = 0;
    bool have = false;
    for (int s = s0; s < send; s++) {
        int mcur = mnext;
        float a0 = q0, a1 = q1, a2 = q2;
        if (s + 1 < send) {
            mnext = mb[s + 1];
            q0 = emb[(s + 1) * 9 + j0];
            q1 = emb[(s + 1) * 9 + j1];
            q2 = act2 ? emb[(s + 1) * 9 + j2] : 0.f;
        }
        if (mcur == 0) continue;         // uniform per warp
        float x0 = __expf(a0);
        float x1 = __expf(a1);
        float x2 = act2 ? __expf(a2) : 0.f;
        if (!have) {
            float* E = sE[w][cur];
            E[e0] = eTd0 * x0;
            E[e1] = eTd1 * x1;
            if (act2) E[e2] = eTd2 * x2;
            have = true;
            __syncwarp();
        } else {
            const float* E = sE[w][cur];
            float* En = sE[w][cur ^ 1];
            float r0 = 0.f, r1 = 0.f, r2 = 0.f;
#pragma unroll
            for (int k = 0; k < 9; k++) {
                r0 += E[i0 * 9 + k] * eT0[k];
                r1 += E[i1 * 9 + k] * eT1[k];
                if (act2) r2 += E[i2 * 9 + k] * eT2[k];
            }
            En[e0] = r0 * x0;
            En[e1] = r1 * x1;
            if (act2) En[e2] = r2 * x2;
            cur ^= 1;
            __syncwarp();
        }
    }

    // normalize into compact bufA, keep log(max)
    float* outm = bufA + w * 81;
    if (have) {
        const float* E = sE[w][cur];
        float v0 = E[e0], v1 = E[e1], v2 = act2 ? E[e2] : 0.f;
        float m = fmaxf(fmaxf(v0, v1), v2);
        m = fmaxf(m, __shfl_xor_sync(0xffffffffu, m, 1));
        m = fmaxf(m, __shfl_xor_sync(0xffffffffu, m, 2));
        m = fmaxf(m, __shfl_xor_sync(0xffffffffu, m, 4));
        m = fmaxf(m, __shfl_xor_sync(0xffffffffu, m, 8));
        m = fmaxf(m, __shfl_xor_sync(0xffffffffu, m, 16));
        m = fmaxf(m, 1e-35f);
        float rcp = 1.f / m;
        outm[e0] = v0 * rcp; outm[e1] = v1 * rcp; if (act2) outm[e2] = v2 * rcp;
        if (lane == 0) slog[w] = __logf(m);
    } else {                             // exact identity (chunk fully masked)
        outm[e0] = (i0 == j0) ? 1.f : 0.f;
        outm[e1] = (i1 == j1) ? 1.f : 0.f;
        if (act2) outm[e2] = (i2 == j2) ? 1.f : 0.f;
        if (lane == 0) slog[w] = 0.f;
    }
    __syncthreads();

    // ---- 4-level tree: 16 -> 1, each product scaled by 1/9 ----
    float* src = bufA;
    float* dst = bufB;
    for (int np = 8; np >= 1; np >>= 1) {
        for (int e = tid; e < np * 81; e += 512) {
            int pp = e / 81, r = e % 81, i = r / 9, j = r % 9;
            const float* Am = src + 2 * pp * 81;
            const float* Bm = src + (2 * pp + 1) * 81;
            float s = 0.f;
#pragma unroll
            for (int k = 0; k < 9; k++) s += Am[i * 9 + k] * Bm[k * 9 + j];
            dst[e] = s * (1.f / 9.f);
        }
        __syncthreads();
        float* t = src; src = dst; dst = t;
    }
    // half-matrix in src[0..81)

    for (int e = tid; e < 81; e += 512) g_half[blk * 81 + e] = src[e];
    if (w == 0) {
        float lg = (lane < 16) ? slog[lane] : 0.f;
#pragma unroll
        for (int o = 8; o > 0; o >>= 1) lg += __shfl_xor_sync(0xffffffffu, lg, o);
        if (lane == 0) {
            g_hlog[blk] = lg;
            __threadfence();
            int old = atomicAdd(&g_cnt, 1);
            if (old == 127) sflag = 1;
        }
    }
    __syncthreads();
    if (!sflag) return;

    // ---- last-arriving block: combine halves + finalize everything ----
    if (tid < Bn) sZ[tid] = 0.f;
    for (int idx = tid; idx < Bn * Ln; idx += 512) {
        int b2 = idx / Ln, i = idx % Ln;
        sa0[idx] = __expf(startT[i] + g_em[(size_t)b2 * Sn * Ln + i]);
    }
    if (tid >= 128 && tid < 128 + Ln) see[tid - 128] = __expf(endT[tid - 128]);
    // mask counts + end transition per batch (warp per batch, strided)
    for (int b2 = w; b2 < Bn; b2 += 16) {
        int cnt = 0;
        for (int t = 0; t < 16; t++) {
            int mk = (mask[b2 * Sn + t * 32 + lane] != 0);
            cnt += __popc(__ballot_sync(0xffffffffu, mk));
        }
        if (lane == 0) sEndT[b2] = endT[tags[b2 * Sn + max(cnt, 1) - 1]];
    }
    __syncthreads();

    for (int idx = tid; idx < Bn * 81; idx += 512) {
        int b2 = idx / 81, r = idx % 81, i = r / 9, j = r % 9;
        const float* Am = g_half + (2 * b2) * 81;
        const float* Bm = g_half + (2 * b2 + 1) * 81;
        float s = 0.f;
#pragma unroll
        for (int k = 0; k < 9; k++) s += Am[i * 9 + k] * Bm[k * 9 + j];
        atomicAdd(&sZ[b2], sa0[b2 * Ln + i] * s * see[j]);
    }
    __syncthreads();

    // total = sum_b (logZ_b - endT term) - sum g_part   (30*ln9 tree scaling)
    float v = 0.f;
    if (tid < Bn)
        v = __logf(sZ[tid]) + 65.91673732f + g_hlog[2 * tid] + g_hlog[2 * tid + 1] - sEndT[tid];
    else if (tid < Bn + GEMM_GRID)
        v = -g_part[tid - Bn];
#pragma unroll
    for (int o = 16; o > 0; o >>= 1) v += __shfl_xor_sync(0xffffffffu, v, o);
    if (lane == 0) sred2[w] = v;
    __syncthreads();
    if (w == 0) {
        float t = (lane < 16) ? sred2[lane] : 0.f;
#pragma unroll
        for (int o = 8; o > 0; o >>= 1) t += __shfl_xor_sync(0xffffffffu, t, o);
        if (lane == 0) out[0] = t;
    }
}

// ---------------------------------------------------------------------------
extern "C" void kernel_launch(void* const* d_in, const int* in_sizes, int n_in,
                              void* d_out, int out_size) {
    const float* x      = (const float*)d_in[0];   // (64,512,1024) f32
    const int*   tags   = (const int*)d_in[1];     // (64,512) i32
    const int*   mask   = (const int*)d_in[2];     // (64,512) bool -> i32
    const float* W      = (const float*)d_in[3];   // (9,1024) f32
    const float* bias   = (const float*)d_in[4];   // (9,)
    const float* startT = (const float*)d_in[5];   // (9,)
    const float* endT   = (const float*)d_in[6];   // (9,)
    const float* T      = (const float*)d_in[7];   // (9,9)

    k_gemm<<<GEMM_GRID, 512>>>(x, W, bias, tags, mask, startT, T);
    k_crf <<<128, 512>>>(tags, mask, startT, endT, T, (float*)d_out);
}